// round 1
// baseline (speedup 1.0000x reference)
#include <cuda_runtime.h>
#include <math.h>

// Problem constants
#define B_    8
#define S_    512
#define H_    4096
#define HQ_   32
#define HKV_  8
#define D_    128
#define L_    1536
#define T_    2048          // L_ + S_
#define NT_   (B_*S_)       // 4096 tokens
#define THETA_ 500000.0f

// ---------------- scratch (device globals; no runtime allocation) ----------
__device__ float g_q   [(size_t)NT_*HQ_ *D_];   // 4096 x 4096
__device__ float g_ktmp[(size_t)NT_*HKV_*D_];   // 4096 x 1024
__device__ float g_vtmp[(size_t)NT_*HKV_*D_];   // 4096 x 1024
__device__ float g_K   [(size_t)B_*T_*HKV_*D_]; // 8 x 2048 x 8 x 128
__device__ float g_V   [(size_t)B_*T_*HKV_*D_];
__device__ float g_att [(size_t)NT_*HQ_ *D_];   // 4096 x 4096

// ---------------- SGEMM: C[M,N] = A[M,K] @ B[K,N], row-major, fp32 ---------
// 128x128 tile, BK=8, 256 threads, 8x8 per-thread register tile.
__global__ __launch_bounds__(256) void sgemm_kernel(
    const float* __restrict__ A, const float* __restrict__ B,
    float* __restrict__ C, int M, int N, int K)
{
    __shared__ float As[8][128];
    __shared__ float Bs[8][128];

    const int tid = threadIdx.x;
    const int bm  = blockIdx.y * 128;
    const int bn  = blockIdx.x * 128;

    const int aRow = tid >> 1;          // 0..127
    const int aCol = (tid & 1) * 4;     // 0 or 4
    const int bRow = tid >> 5;          // 0..7
    const int bCol = (tid & 31) * 4;    // 0..124

    const int ty = tid >> 4;            // 0..15 -> rows ty*8
    const int tx = tid & 15;            // 0..15 -> cols tx*8

    float acc[8][8];
#pragma unroll
    for (int i = 0; i < 8; i++)
#pragma unroll
        for (int j = 0; j < 8; j++) acc[i][j] = 0.0f;

    for (int k0 = 0; k0 < K; k0 += 8) {
        float4 av = *reinterpret_cast<const float4*>(&A[(size_t)(bm + aRow) * K + k0 + aCol]);
        As[aCol + 0][aRow] = av.x;
        As[aCol + 1][aRow] = av.y;
        As[aCol + 2][aRow] = av.z;
        As[aCol + 3][aRow] = av.w;
        float4 bv = *reinterpret_cast<const float4*>(&B[(size_t)(k0 + bRow) * N + bn + bCol]);
        *reinterpret_cast<float4*>(&Bs[bRow][bCol]) = bv;
        __syncthreads();

#pragma unroll
        for (int kk = 0; kk < 8; kk++) {
            float4 a0 = *reinterpret_cast<const float4*>(&As[kk][ty * 8]);
            float4 a1 = *reinterpret_cast<const float4*>(&As[kk][ty * 8 + 4]);
            float4 b0 = *reinterpret_cast<const float4*>(&Bs[kk][tx * 8]);
            float4 b1 = *reinterpret_cast<const float4*>(&Bs[kk][tx * 8 + 4]);
            float ra[8] = {a0.x, a0.y, a0.z, a0.w, a1.x, a1.y, a1.z, a1.w};
            float rb[8] = {b0.x, b0.y, b0.z, b0.w, b1.x, b1.y, b1.z, b1.w};
#pragma unroll
            for (int i = 0; i < 8; i++)
#pragma unroll
                for (int j = 0; j < 8; j++)
                    acc[i][j] += ra[i] * rb[j];
        }
        __syncthreads();
    }

#pragma unroll
    for (int i = 0; i < 8; i++) {
        float* crow = &C[(size_t)(bm + ty * 8 + i) * N + bn + tx * 8];
        float4 v0 = make_float4(acc[i][0], acc[i][1], acc[i][2], acc[i][3]);
        float4 v1 = make_float4(acc[i][4], acc[i][5], acc[i][6], acc[i][7]);
        *reinterpret_cast<float4*>(crow)     = v0;
        *reinterpret_cast<float4*>(crow + 4) = v1;
    }
}

// ---------------- RoPE on Q (in place) -------------------------------------
// one thread per (token, head, d-pair); total NT_*HQ_*64
__global__ void rope_q_kernel()
{
    int idx = blockIdx.x * blockDim.x + threadIdx.x;
    if (idx >= NT_ * HQ_ * 64) return;
    int d   = idx & 63;
    int th  = idx >> 6;          // token*HQ + h
    int tok = th >> 5;           // HQ_ == 32
    int s   = tok & (S_ - 1);
    float pos = (float)(L_ + s);
    float inv = powf(THETA_, -(float)d * (1.0f / 64.0f));
    float ang = pos * inv;
    float c = cosf(ang), sn = sinf(ang);
    float* base = g_q + (size_t)th * D_;
    float x1 = base[d], x2 = base[d + 64];
    base[d]      = x1 * c - x2 * sn;
    base[d + 64] = x2 * c + x1 * sn;
}

// ---------------- RoPE on new K + scatter into combined K buffer -----------
__global__ void rope_scatter_k_kernel()
{
    int idx = blockIdx.x * blockDim.x + threadIdx.x;
    if (idx >= NT_ * HKV_ * 64) return;
    int d   = idx & 63;
    int th  = idx >> 6;          // token*HKV + kv
    int tok = th >> 3;           // HKV_ == 8
    int kvh = th & 7;
    int b   = tok >> 9;          // S_ == 512
    int s   = tok & 511;
    float pos = (float)(L_ + s);
    float inv = powf(THETA_, -(float)d * (1.0f / 64.0f));
    float ang = pos * inv;
    float c = cosf(ang), sn = sinf(ang);
    const float* src = g_ktmp + (size_t)th * D_;
    float* dst = g_K + (((size_t)(b * T_ + L_ + s)) * HKV_ + kvh) * D_;
    float x1 = src[d], x2 = src[d + 64];
    dst[d]      = x1 * c - x2 * sn;
    dst[d + 64] = x2 * c + x1 * sn;
}

// ---------------- scatter new V into combined V buffer (float4) ------------
__global__ void scatter_v_kernel()
{
    int idx = blockIdx.x * blockDim.x + threadIdx.x;
    const int n = NT_ * HKV_ * D_ / 4;
    if (idx >= n) return;
    const int per = HKV_ * D_ / 4;   // 256
    int tok = idx / per;
    int r   = idx - tok * per;
    int b   = tok >> 9;
    int s   = tok & 511;
    const float4* src = reinterpret_cast<const float4*>(g_vtmp);
    float4* dst = reinterpret_cast<float4*>(g_V);
    dst[((size_t)(b * T_ + L_ + s)) * per + r] = src[idx];
}

// ---------------- copy K/V cache into combined buffers (float4) ------------
__global__ void copy_cache_kernel(const float4* __restrict__ kc,
                                  const float4* __restrict__ vc)
{
    int idx = blockIdx.x * blockDim.x + threadIdx.x;
    const int n = B_ * L_ * HKV_ * D_ / 4;
    if (idx >= n) return;
    const int perb_src = L_ * HKV_ * D_ / 4;
    const int perb_dst = T_ * HKV_ * D_ / 4;
    int b = idx / perb_src;
    int r = idx - b * perb_src;
    float4* dk = reinterpret_cast<float4*>(g_K);
    float4* dv = reinterpret_cast<float4*>(g_V);
    dk[(size_t)b * perb_dst + r] = kc[idx];
    dv[(size_t)b * perb_dst + r] = vc[idx];
}

// ---------------- flash attention, fp32, 64q x 64k tiles -------------------
// grid (S/64=8, HQ=32, B=8), 256 threads.
// smem: Qs[64][129] Ks[64][129] Vs[64][129] Ss[64][65] m[64] l[64] f[64]
#define ATT_SMEM_FLOATS (3 * 64 * 129 + 64 * 65 + 3 * 64)
#define ATT_SMEM_BYTES  (ATT_SMEM_FLOATS * 4)

__global__ __launch_bounds__(256) void attn_kernel()
{
    extern __shared__ float sm[];
    float* Qs   = sm;
    float* Ks   = sm + 64 * 129;
    float* Vs   = sm + 2 * 64 * 129;
    float* Ss   = sm + 3 * 64 * 129;
    float* m_sh = Ss + 64 * 65;
    float* l_sh = m_sh + 64;
    float* f_sh = l_sh + 64;

    const int tid = threadIdx.x;
    const int qt  = blockIdx.x;     // query tile (0..7)
    const int hq  = blockIdx.y;     // q head
    const int b   = blockIdx.z;     // batch
    const int kvh = hq >> 2;        // GQA group of 4
    const int s0  = qt * 64;

    const int lr = tid >> 2;          // loader row 0..63
    const int lc = (tid & 3) * 32;    // loader col base

    // load Q tile (rows = queries, cols = head dim)
    {
        const float* src = g_q + ((size_t)(b * S_ + s0 + lr)) * (HQ_ * D_) + hq * D_ + lc;
        float* dq = Qs + lr * 129 + lc;
#pragma unroll
        for (int i = 0; i < 32; i += 4) {
            float4 v = *reinterpret_cast<const float4*>(src + i);
            dq[i] = v.x; dq[i + 1] = v.y; dq[i + 2] = v.z; dq[i + 3] = v.w;
        }
    }
    if (tid < 64) { m_sh[tid] = -1e30f; l_sh[tid] = 0.0f; }

    const int ty = tid >> 4;   // 0..15 : owns score rows ty*4..+3 and O rows ty*4..+3
    const int tx = tid & 15;   // 0..15 : score cols tx*4..+3 ; O cols tx*8..+7

    float acc[4][8];
#pragma unroll
    for (int i = 0; i < 4; i++)
#pragma unroll
        for (int j = 0; j < 8; j++) acc[i][j] = 0.0f;

    const int ntiles = 25 + qt;   // L/64 = 24 cache tiles + (qt+1) new tiles

    for (int kt = 0; kt < ntiles; kt++) {
        __syncthreads();
        // load K tile
        {
            const float* src = g_K + (((size_t)(b * T_ + kt * 64 + lr)) * HKV_ + kvh) * D_ + lc;
            float* dk = Ks + lr * 129 + lc;
#pragma unroll
            for (int i = 0; i < 32; i += 4) {
                float4 v = *reinterpret_cast<const float4*>(src + i);
                dk[i] = v.x; dk[i + 1] = v.y; dk[i + 2] = v.z; dk[i + 3] = v.w;
            }
        }
        __syncthreads();

        // scores: 4x4 register tile per thread over d=0..127
        float aS[4][4];
#pragma unroll
        for (int i = 0; i < 4; i++)
#pragma unroll
            for (int j = 0; j < 4; j++) aS[i][j] = 0.0f;

        const float* qb = Qs + (ty * 4) * 129;
        const float* kb = Ks + (tx * 4) * 129;
#pragma unroll 4
        for (int d = 0; d < 128; d++) {
            float ra[4], rb[4];
#pragma unroll
            for (int i = 0; i < 4; i++) ra[i] = qb[i * 129 + d];
#pragma unroll
            for (int j = 0; j < 4; j++) rb[j] = kb[j * 129 + d];
#pragma unroll
            for (int i = 0; i < 4; i++)
#pragma unroll
                for (int j = 0; j < 4; j++)
                    aS[i][j] += ra[i] * rb[j];
        }

        const bool diag = (kt == ntiles - 1);
        const float scl = 0.08838834764831845f;   // 1/sqrt(128)
#pragma unroll
        for (int i = 0; i < 4; i++) {
            int row = ty * 4 + i;
#pragma unroll
            for (int j = 0; j < 4; j++) {
                int col = tx * 4 + j;
                float v = aS[i][j] * scl;
                if (diag && col > row) v = -1e30f;
                Ss[row * 65 + col] = v;
            }
        }
        __syncthreads();

        // online softmax, one thread per row
        if (tid < 64) {
            float mold = m_sh[tid];
            float mx = mold;
            float* sr = Ss + tid * 65;
            for (int j = 0; j < 64; j++) mx = fmaxf(mx, sr[j]);
            float sum = 0.0f;
            for (int j = 0; j < 64; j++) {
                float p = expf(sr[j] - mx);
                sr[j] = p;
                sum += p;
            }
            float f = expf(mold - mx);
            l_sh[tid] = l_sh[tid] * f + sum;
            m_sh[tid] = mx;
            f_sh[tid] = f;
        }
        __syncthreads();

        // rescale accumulators, and load V tile
#pragma unroll
        for (int i = 0; i < 4; i++) {
            float f = f_sh[ty * 4 + i];
#pragma unroll
            for (int n = 0; n < 8; n++) acc[i][n] *= f;
        }
        {
            const float* src = g_V + (((size_t)(b * T_ + kt * 64 + lr)) * HKV_ + kvh) * D_ + lc;
            float* dv = Vs + lr * 129 + lc;
#pragma unroll
            for (int i = 0; i < 32; i += 4) {
                float4 v = *reinterpret_cast<const float4*>(src + i);
                dv[i] = v.x; dv[i + 1] = v.y; dv[i + 2] = v.z; dv[i + 3] = v.w;
            }
        }
        __syncthreads();

        // O += P @ V : per-thread 4 rows x 8 cols
        const float* pb = Ss + (ty * 4) * 65;
        const float* vb = Vs + tx * 8;
#pragma unroll 2
        for (int j = 0; j < 64; j++) {
            float p0 = pb[j];
            float p1 = pb[65 + j];
            float p2 = pb[130 + j];
            float p3 = pb[195 + j];
            const float* vr = vb + j * 129;
#pragma unroll
            for (int n = 0; n < 8; n++) {
                float v = vr[n];
                acc[0][n] += p0 * v;
                acc[1][n] += p1 * v;
                acc[2][n] += p2 * v;
                acc[3][n] += p3 * v;
            }
        }
    }

    __syncthreads();
    float li[4];
#pragma unroll
    for (int i = 0; i < 4; i++) li[i] = 1.0f / l_sh[ty * 4 + i];

    float* dst = g_att + ((size_t)(b * S_ + s0 + ty * 4)) * (HQ_ * D_) + hq * D_ + tx * 8;
#pragma unroll
    for (int i = 0; i < 4; i++) {
        float4 v0 = make_float4(acc[i][0] * li[i], acc[i][1] * li[i],
                                acc[i][2] * li[i], acc[i][3] * li[i]);
        float4 v1 = make_float4(acc[i][4] * li[i], acc[i][5] * li[i],
                                acc[i][6] * li[i], acc[i][7] * li[i]);
        *reinterpret_cast<float4*>(dst + (size_t)i * (HQ_ * D_))     = v0;
        *reinterpret_cast<float4*>(dst + (size_t)i * (HQ_ * D_) + 4) = v1;
    }
}

// ---------------- launcher --------------------------------------------------
extern "C" void kernel_launch(void* const* d_in, const int* in_sizes, int n_in,
                              void* d_out, int out_size)
{
    const float* hidden  = (const float*)d_in[0];
    const float* k_cache = (const float*)d_in[1];
    const float* v_cache = (const float*)d_in[2];
    const float* wq      = (const float*)d_in[3];
    const float* wk      = (const float*)d_in[4];
    const float* wv      = (const float*)d_in[5];
    const float* wo      = (const float*)d_in[6];
    float* out = (float*)d_out;

    float *q, *ktmp, *vtmp, *att;
    cudaGetSymbolAddress((void**)&q,    g_q);
    cudaGetSymbolAddress((void**)&ktmp, g_ktmp);
    cudaGetSymbolAddress((void**)&vtmp, g_vtmp);
    cudaGetSymbolAddress((void**)&att,  g_att);

    cudaFuncSetAttribute(attn_kernel,
                         cudaFuncAttributeMaxDynamicSharedMemorySize,
                         ATT_SMEM_BYTES);

    dim3 blk(256);

    // projections
    sgemm_kernel<<<dim3(H_ / 128, NT_ / 128), blk>>>(hidden, wq, q,    NT_, H_,         H_);
    sgemm_kernel<<<dim3((HKV_ * D_) / 128, NT_ / 128), blk>>>(hidden, wk, ktmp, NT_, HKV_ * D_, H_);
    sgemm_kernel<<<dim3((HKV_ * D_) / 128, NT_ / 128), blk>>>(hidden, wv, vtmp, NT_, HKV_ * D_, H_);

    // rope + KV assembly
    rope_q_kernel<<<(NT_ * HQ_ * 64) / 256, 256>>>();
    rope_scatter_k_kernel<<<(NT_ * HKV_ * 64) / 256, 256>>>();
    scatter_v_kernel<<<(NT_ * HKV_ * D_ / 4) / 256, 256>>>();
    copy_cache_kernel<<<(B_ * L_ * HKV_ * D_ / 4) / 256, 256>>>(
        (const float4*)k_cache, (const float4*)v_cache);

    // attention
    attn_kernel<<<dim3(S_ / 64, HQ_, B_), blk, ATT_SMEM_BYTES>>>();

    // output projection
    sgemm_kernel<<<dim3(H_ / 128, NT_ / 128), blk>>>(att, wo, out, NT_, H_, H_);
}